// round 6
// baseline (speedup 1.0000x reference)
#include <cuda_runtime.h>
#include <cstdint>
#include <math.h>

// Problem constants (fixed by the reference): N=8192 nodes, F=512 features, H=2.
#define NNODE 8192
#define FDIM  512
#define C2    1024

// ---------------- scratch (static __device__ — no allocations) ----------------
__device__ float g_C [(size_t)NNODE * C2];     // X @ W            [8192,1024]  33.5 MB
__device__ float g_Wh[(size_t)NNODE * FDIM];   // Wh               [8192,512]   16 MB
__device__ float g_T [(size_t)NNODE * FDIM];   // tanh(Wh+Ws+b)    [8192,512]   16 MB
__device__ float g_S [(size_t)NNODE * NNODE];  // scores/attn      [8192,8192]  268 MB
__device__ float g_O [(size_t)NNODE * FDIM];   // attn@Wh + X      [8192,512]   16 MB
__device__ float g_psum[32 * FDIM];
__device__ float g_psq [32 * FDIM];
__device__ float g_mean[FDIM];
__device__ float g_rstd[FDIM];

// ---------------- 128x128x8 fp32 GEMM, 256 threads, 8x8 microtiles ----------------
// TRANSB=false: C[M,N] = A[M,K] @ B[K,N]   (+ optional residual)
// TRANSB=true : C[M,N] = A[M,K] @ B[N,K]^T
// All of M,N multiples of 128; K multiple of 8 (holds for every call here).
template<bool TRANSB>
__global__ __launch_bounds__(256, 2)
void sgemm128(const float* __restrict__ A, const float* __restrict__ B,
              float* __restrict__ C, const float* __restrict__ resid,
              int M, int N, int K)
{
    __shared__ float As[8][132];   // pad 132: conflict-free transposed stores
    __shared__ float Bs[8][132];

    const int tid = threadIdx.x;
    const int bx = blockIdx.x, by = blockIdx.y;
    const int tx = tid & 15, ty = tid >> 4;

    float acc[8][8];
#pragma unroll
    for (int i = 0; i < 8; i++)
#pragma unroll
        for (int j = 0; j < 8; j++) acc[i][j] = 0.f;

    // A tile loader: 128 rows x 8 K-cols, one float4 per thread, stored transposed.
    const int aRow = tid >> 1;
    const int aCol = (tid & 1) * 4;
    const float* Ap = A + (size_t)(by * 128 + aRow) * K + aCol;

    const float* Bp;
    int bRow, bCol;
    if (TRANSB) {
        bRow = tid >> 1; bCol = (tid & 1) * 4;          // B[N,K]: like A
        Bp = B + (size_t)(bx * 128 + bRow) * K + bCol;
    } else {
        bRow = tid >> 5; bCol = (tid & 31) * 4;         // B[K,N]: 8 rows x 128 cols
        Bp = B + (size_t)bRow * N + (size_t)bx * 128 + bCol;
    }

    // prefetch first slab
    float4 av = *(const float4*)Ap;
    float4 bv = *(const float4*)Bp;
    Ap += 8;
    Bp += TRANSB ? 8 : (size_t)8 * N;

    for (int k0 = 0; k0 < K; k0 += 8) {
        __syncthreads();
        As[aCol + 0][aRow] = av.x;
        As[aCol + 1][aRow] = av.y;
        As[aCol + 2][aRow] = av.z;
        As[aCol + 3][aRow] = av.w;
        if (TRANSB) {
            Bs[bCol + 0][bRow] = bv.x;
            Bs[bCol + 1][bRow] = bv.y;
            Bs[bCol + 2][bRow] = bv.z;
            Bs[bCol + 3][bRow] = bv.w;
        } else {
            *(float4*)&Bs[bRow][bCol] = bv;
        }
        __syncthreads();

        if (k0 + 8 < K) {   // prefetch next slab: LDG latency overlaps compute
            av = *(const float4*)Ap;
            bv = *(const float4*)Bp;
            Ap += 8;
            Bp += TRANSB ? 8 : (size_t)8 * N;
        }

#pragma unroll
        for (int kk = 0; kk < 8; kk++) {
            float4 a0 = *(const float4*)&As[kk][ty * 4];
            float4 a1 = *(const float4*)&As[kk][ty * 4 + 64];
            float4 b0 = *(const float4*)&Bs[kk][tx * 4];
            float4 b1 = *(const float4*)&Bs[kk][tx * 4 + 64];
            float am[8] = {a0.x, a0.y, a0.z, a0.w, a1.x, a1.y, a1.z, a1.w};
            float bn[8] = {b0.x, b0.y, b0.z, b0.w, b1.x, b1.y, b1.z, b1.w};
#pragma unroll
            for (int i = 0; i < 8; i++)
#pragma unroll
                for (int j = 0; j < 8; j++)
                    acc[i][j] += am[i] * bn[j];
        }
    }

    const int row0 = by * 128, col0 = bx * 128;
    const int c0 = tx * 4, c1 = tx * 4 + 64;
#pragma unroll
    for (int i = 0; i < 8; i++) {
        int r = row0 + ty * 4 + (i < 4 ? i : i + 60);   // rows {t4..t4+3, t4+64..+67}
        size_t base = (size_t)r * N + col0;
        float4 v0 = make_float4(acc[i][0], acc[i][1], acc[i][2], acc[i][3]);
        float4 v1 = make_float4(acc[i][4], acc[i][5], acc[i][6], acc[i][7]);
        if (resid) {
            float4 r0 = *(const float4*)&resid[base + c0];
            float4 r1 = *(const float4*)&resid[base + c1];
            v0.x += r0.x; v0.y += r0.y; v0.z += r0.z; v0.w += r0.w;
            v1.x += r1.x; v1.y += r1.y; v1.z += r1.z; v1.w += r1.w;
        }
        *(float4*)&C[base + c0] = v0;
        *(float4*)&C[base + c1] = v1;
    }
}

// ---------------- split C -> Wh and T = tanh(Wh + Ws + bias) ----------------
__global__ void prep_kernel(const float* __restrict__ aw, const float* __restrict__ ab)
{
    const float bias = aw[0] + ab[0];
    int idx = blockIdx.x * blockDim.x + threadIdx.x;
    int row = idx >> 9, col = idx & 511;
    float wh = g_C[(size_t)row * C2 + col];
    float ws = g_C[(size_t)row * C2 + col + FDIM];
    g_Wh[idx] = wh;
    g_T[idx]  = tanhf(wh + ws + bias);
}

// ---------------- in-place row softmax (online max/sum, 1 block per row) ------
__global__ void softmax_row(float* __restrict__ S, int N)
{
    const int row = blockIdx.x;
    float* p = S + (size_t)row * N;
    const int tid = threadIdx.x;

    float m = -1e30f, s = 0.f;
    for (int i = tid; i < N; i += 256) {
        float x = p[i];
        float mn = fmaxf(m, x);
        s = s * __expf(m - mn) + __expf(x - mn);
        m = mn;
    }
    __shared__ float sm[256], ss[256];
    sm[tid] = m; ss[tid] = s;
    __syncthreads();
    for (int off = 128; off > 0; off >>= 1) {
        if (tid < off) {
            float m2 = sm[tid + off], s2 = ss[tid + off];
            float mn = fmaxf(sm[tid], m2);
            ss[tid] = ss[tid] * __expf(sm[tid] - mn) + s2 * __expf(m2 - mn);
            sm[tid] = mn;
        }
        __syncthreads();
    }
    const float M = sm[0];
    const float inv = 1.f / ss[0];
    for (int i = tid; i < N; i += 256)
        p[i] = __expf(p[i] - M) * inv;
}

// ---------------- column stats: per-feature sum / sumsq (partials) ------------
__global__ void colstats(void)
{
    const int tid = threadIdx.x;
    const int c = blockIdx.x * 128 + (tid & 127);
    const int rl = tid >> 7;                 // 0/1
    const int r0 = blockIdx.y * 256;
    float s = 0.f, q = 0.f;
    for (int r = r0 + rl; r < r0 + 256; r += 2) {
        float v = g_O[(size_t)r * FDIM + c];
        s += v; q += v * v;
    }
    __shared__ float sh[256], shq[256];
    sh[tid] = s; shq[tid] = q;
    __syncthreads();
    if (tid < 128) {
        g_psum[blockIdx.y * FDIM + c] = sh[tid] + sh[tid + 128];
        g_psq [blockIdx.y * FDIM + c] = shq[tid] + shq[tid + 128];
    }
}

__global__ void finalize_stats(void)
{
    const int c = threadIdx.x;
    float s = 0.f, q = 0.f;
    for (int j = 0; j < 32; j++) {
        s += g_psum[j * FDIM + c];
        q += g_psq [j * FDIM + c];
    }
    float mean = s * (1.f / (float)NNODE);
    float var  = q * (1.f / (float)NNODE) - mean * mean;
    g_mean[c] = mean;
    g_rstd[c] = rsqrtf(var + 1e-5f);
}

// ---------------- batchnorm (no affine) + leaky relu -> d_out -----------------
__global__ void normalize_out(float* __restrict__ out)
{
    int idx = blockIdx.x * blockDim.x + threadIdx.x;
    int c = idx & 511;
    float v = (g_O[idx] - g_mean[c]) * g_rstd[c];
    out[idx] = v >= 0.f ? v : 0.01f * v;
}

// ---------------- launch --------------------------------------------------------
extern "C" void kernel_launch(void* const* d_in, const int* in_sizes, int n_in,
                              void* d_out, int out_size)
{
    // Identify inputs by element count (robust to ordering). bias = a_w+a_b is
    // symmetric, so the two scalars need no disambiguation.
    const float* X = nullptr;
    const float* W = nullptr;
    const float* s1 = nullptr;
    const float* s2 = nullptr;
    for (int i = 0; i < n_in; i++) {
        if (in_sizes[i] == NNODE * FDIM)      X = (const float*)d_in[i];
        else if (in_sizes[i] == FDIM * C2)    W = (const float*)d_in[i];
        else if (in_sizes[i] == 1) { if (!s1) s1 = (const float*)d_in[i]; else s2 = (const float*)d_in[i]; }
        // adj (NNODE*NNODE) is unused by the reference module
    }

    float *pC, *pWh, *pT, *pS, *pO;
    cudaGetSymbolAddress((void**)&pC,  g_C);
    cudaGetSymbolAddress((void**)&pWh, g_Wh);
    cudaGetSymbolAddress((void**)&pT,  g_T);
    cudaGetSymbolAddress((void**)&pS,  g_S);
    cudaGetSymbolAddress((void**)&pO,  g_O);

    const dim3 blk(256);

    // 1) C = X @ W                     [8192,512] @ [512,1024]
    sgemm128<false><<<dim3(C2 / 128, NNODE / 128), blk>>>(X, W, pC, nullptr,
                                                          NNODE, C2, FDIM);
    // 2) Wh split; T = tanh(Wh+Ws+bias)
    prep_kernel<<<(NNODE * FDIM) / 256, 256>>>(s1, s2);

    // 3) S = T @ Wh^T                  [8192,512] @ [8192,512]^T
    sgemm128<true><<<dim3(NNODE / 128, NNODE / 128), blk>>>(pT, pWh, pS, nullptr,
                                                            NNODE, NNODE, FDIM);
    // 4) row softmax in place
    softmax_row<<<NNODE, 256>>>(pS, NNODE);

    // 5) O = S @ Wh + X                [8192,8192] @ [8192,512]
    sgemm128<false><<<dim3(FDIM / 128, NNODE / 128), blk>>>(pS, pWh, pO, X,
                                                            NNODE, FDIM, NNODE);
    // 6) batchnorm stats + 7) normalize + leaky relu
    colstats<<<dim3(FDIM / 128, 32), 256>>>();
    finalize_stats<<<1, FDIM>>>();
    normalize_out<<<(NNODE * FDIM) / 256, 256>>>((float*)d_out);
}

// round 7
// speedup vs baseline: 1.0004x; 1.0004x over previous
#include <cuda_runtime.h>
#include <cstdint>
#include <math.h>

// Problem constants (fixed by the reference): N=8192 nodes, F=512 features, H=2.
#define NNODE 8192
#define FDIM  512
#define C2    1024

// ---------------- scratch (static __device__ — no allocations) ----------------
__device__ float g_C [(size_t)NNODE * C2];     // X @ W            [8192,1024]  33.5 MB
__device__ float g_Wh[(size_t)NNODE * FDIM];   // Wh               [8192,512]   16 MB
__device__ float g_T [(size_t)NNODE * FDIM];   // tanh(Wh+Ws+b)    [8192,512]   16 MB
__device__ float g_S [(size_t)NNODE * NNODE];  // scores/attn      [8192,8192]  268 MB
__device__ float g_O [(size_t)NNODE * FDIM];   // attn@Wh + X      [8192,512]   16 MB
__device__ float g_psum[32 * FDIM];
__device__ float g_psq [32 * FDIM];
__device__ float g_mean[FDIM];
__device__ float g_rstd[FDIM];

// ---------------- 128x128x8 fp32 GEMM, 256 threads, 8x8 microtiles ----------------
// TRANSB=false: C[M,N] = A[M,K] @ B[K,N]   (+ optional residual)
// TRANSB=true : C[M,N] = A[M,K] @ B[N,K]^T
// All of M,N multiples of 128; K multiple of 8 (holds for every call here).
template<bool TRANSB>
__global__ __launch_bounds__(256, 2)
void sgemm128(const float* __restrict__ A, const float* __restrict__ B,
              float* __restrict__ C, const float* __restrict__ resid,
              int M, int N, int K)
{
    __shared__ float As[8][132];   // pad 132: conflict-free transposed stores
    __shared__ float Bs[8][132];

    const int tid = threadIdx.x;
    const int bx = blockIdx.x, by = blockIdx.y;
    const int tx = tid & 15, ty = tid >> 4;

    float acc[8][8];
#pragma unroll
    for (int i = 0; i < 8; i++)
#pragma unroll
        for (int j = 0; j < 8; j++) acc[i][j] = 0.f;

    // A tile loader: 128 rows x 8 K-cols, one float4 per thread, stored transposed.
    const int aRow = tid >> 1;
    const int aCol = (tid & 1) * 4;
    const float* Ap = A + (size_t)(by * 128 + aRow) * K + aCol;

    const float* Bp;
    int bRow, bCol;
    if (TRANSB) {
        bRow = tid >> 1; bCol = (tid & 1) * 4;          // B[N,K]: like A
        Bp = B + (size_t)(bx * 128 + bRow) * K + bCol;
    } else {
        bRow = tid >> 5; bCol = (tid & 31) * 4;         // B[K,N]: 8 rows x 128 cols
        Bp = B + (size_t)bRow * N + (size_t)bx * 128 + bCol;
    }

    // prefetch first slab
    float4 av = *(const float4*)Ap;
    float4 bv = *(const float4*)Bp;
    Ap += 8;
    Bp += TRANSB ? 8 : (size_t)8 * N;

    for (int k0 = 0; k0 < K; k0 += 8) {
        __syncthreads();
        As[aCol + 0][aRow] = av.x;
        As[aCol + 1][aRow] = av.y;
        As[aCol + 2][aRow] = av.z;
        As[aCol + 3][aRow] = av.w;
        if (TRANSB) {
            Bs[bCol + 0][bRow] = bv.x;
            Bs[bCol + 1][bRow] = bv.y;
            Bs[bCol + 2][bRow] = bv.z;
            Bs[bCol + 3][bRow] = bv.w;
        } else {
            *(float4*)&Bs[bRow][bCol] = bv;
        }
        __syncthreads();

        if (k0 + 8 < K) {   // prefetch next slab: LDG latency overlaps compute
            av = *(const float4*)Ap;
            bv = *(const float4*)Bp;
            Ap += 8;
            Bp += TRANSB ? 8 : (size_t)8 * N;
        }

#pragma unroll
        for (int kk = 0; kk < 8; kk++) {
            float4 a0 = *(const float4*)&As[kk][ty * 4];
            float4 a1 = *(const float4*)&As[kk][ty * 4 + 64];
            float4 b0 = *(const float4*)&Bs[kk][tx * 4];
            float4 b1 = *(const float4*)&Bs[kk][tx * 4 + 64];
            float am[8] = {a0.x, a0.y, a0.z, a0.w, a1.x, a1.y, a1.z, a1.w};
            float bn[8] = {b0.x, b0.y, b0.z, b0.w, b1.x, b1.y, b1.z, b1.w};
#pragma unroll
            for (int i = 0; i < 8; i++)
#pragma unroll
                for (int j = 0; j < 8; j++)
                    acc[i][j] += am[i] * bn[j];
        }
    }

    const int row0 = by * 128, col0 = bx * 128;
    const int c0 = tx * 4, c1 = tx * 4 + 64;
#pragma unroll
    for (int i = 0; i < 8; i++) {
        int r = row0 + ty * 4 + (i < 4 ? i : i + 60);   // rows {t4..t4+3, t4+64..+67}
        size_t base = (size_t)r * N + col0;
        float4 v0 = make_float4(acc[i][0], acc[i][1], acc[i][2], acc[i][3]);
        float4 v1 = make_float4(acc[i][4], acc[i][5], acc[i][6], acc[i][7]);
        if (resid) {
            float4 r0 = *(const float4*)&resid[base + c0];
            float4 r1 = *(const float4*)&resid[base + c1];
            v0.x += r0.x; v0.y += r0.y; v0.z += r0.z; v0.w += r0.w;
            v1.x += r1.x; v1.y += r1.y; v1.z += r1.z; v1.w += r1.w;
        }
        *(float4*)&C[base + c0] = v0;
        *(float4*)&C[base + c1] = v1;
    }
}

// ---------------- split C -> Wh and T = tanh(Wh + Ws + bias) ----------------
__global__ void prep_kernel(const float* __restrict__ aw, const float* __restrict__ ab)
{
    const float bias = aw[0] + ab[0];
    int idx = blockIdx.x * blockDim.x + threadIdx.x;
    int row = idx >> 9, col = idx & 511;
    float wh = g_C[(size_t)row * C2 + col];
    float ws = g_C[(size_t)row * C2 + col + FDIM];
    g_Wh[idx] = wh;
    g_T[idx]  = tanhf(wh + ws + bias);
}

// ---------------- in-place row softmax (online max/sum, 1 block per row) ------
__global__ void softmax_row(float* __restrict__ S, int N)
{
    const int row = blockIdx.x;
    float* p = S + (size_t)row * N;
    const int tid = threadIdx.x;

    float m = -1e30f, s = 0.f;
    for (int i = tid; i < N; i += 256) {
        float x = p[i];
        float mn = fmaxf(m, x);
        s = s * __expf(m - mn) + __expf(x - mn);
        m = mn;
    }
    __shared__ float sm[256], ss[256];
    sm[tid] = m; ss[tid] = s;
    __syncthreads();
    for (int off = 128; off > 0; off >>= 1) {
        if (tid < off) {
            float m2 = sm[tid + off], s2 = ss[tid + off];
            float mn = fmaxf(sm[tid], m2);
            ss[tid] = ss[tid] * __expf(sm[tid] - mn) + s2 * __expf(m2 - mn);
            sm[tid] = mn;
        }
        __syncthreads();
    }
    const float M = sm[0];
    const float inv = 1.f / ss[0];
    for (int i = tid; i < N; i += 256)
        p[i] = __expf(p[i] - M) * inv;
}

// ---------------- column stats: per-feature sum / sumsq (partials) ------------
__global__ void colstats(void)
{
    const int tid = threadIdx.x;
    const int c = blockIdx.x * 128 + (tid & 127);
    const int rl = tid >> 7;                 // 0/1
    const int r0 = blockIdx.y * 256;
    float s = 0.f, q = 0.f;
    for (int r = r0 + rl; r < r0 + 256; r += 2) {
        float v = g_O[(size_t)r * FDIM + c];
        s += v; q += v * v;
    }
    __shared__ float sh[256], shq[256];
    sh[tid] = s; shq[tid] = q;
    __syncthreads();
    if (tid < 128) {
        g_psum[blockIdx.y * FDIM + c] = sh[tid] + sh[tid + 128];
        g_psq [blockIdx.y * FDIM + c] = shq[tid] + shq[tid + 128];
    }
}

__global__ void finalize_stats(void)
{
    const int c = threadIdx.x;
    float s = 0.f, q = 0.f;
    for (int j = 0; j < 32; j++) {
        s += g_psum[j * FDIM + c];
        q += g_psq [j * FDIM + c];
    }
    float mean = s * (1.f / (float)NNODE);
    float var  = q * (1.f / (float)NNODE) - mean * mean;
    g_mean[c] = mean;
    g_rstd[c] = rsqrtf(var + 1e-5f);
}

// ---------------- batchnorm (no affine) + leaky relu -> d_out -----------------
__global__ void normalize_out(float* __restrict__ out)
{
    int idx = blockIdx.x * blockDim.x + threadIdx.x;
    int c = idx & 511;
    float v = (g_O[idx] - g_mean[c]) * g_rstd[c];
    out[idx] = v >= 0.f ? v : 0.01f * v;
}

// ---------------- launch --------------------------------------------------------
extern "C" void kernel_launch(void* const* d_in, const int* in_sizes, int n_in,
                              void* d_out, int out_size)
{
    // Identify inputs by element count (robust to ordering). bias = a_w+a_b is
    // symmetric, so the two scalars need no disambiguation.
    const float* X = nullptr;
    const float* W = nullptr;
    const float* s1 = nullptr;
    const float* s2 = nullptr;
    for (int i = 0; i < n_in; i++) {
        if (in_sizes[i] == NNODE * FDIM)      X = (const float*)d_in[i];
        else if (in_sizes[i] == FDIM * C2)    W = (const float*)d_in[i];
        else if (in_sizes[i] == 1) { if (!s1) s1 = (const float*)d_in[i]; else s2 = (const float*)d_in[i]; }
        // adj (NNODE*NNODE) is unused by the reference module
    }

    float *pC, *pWh, *pT, *pS, *pO;
    cudaGetSymbolAddress((void**)&pC,  g_C);
    cudaGetSymbolAddress((void**)&pWh, g_Wh);
    cudaGetSymbolAddress((void**)&pT,  g_T);
    cudaGetSymbolAddress((void**)&pS,  g_S);
    cudaGetSymbolAddress((void**)&pO,  g_O);

    const dim3 blk(256);

    // 1) C = X @ W                     [8192,512] @ [512,1024]
    sgemm128<false><<<dim3(C2 / 128, NNODE / 128), blk>>>(X, W, pC, nullptr,
                                                          NNODE, C2, FDIM);
    // 2) Wh split; T = tanh(Wh+Ws+bias)
    prep_kernel<<<(NNODE * FDIM) / 256, 256>>>(s1, s2);

    // 3) S = T @ Wh^T                  [8192,512] @ [8192,512]^T
    sgemm128<true><<<dim3(NNODE / 128, NNODE / 128), blk>>>(pT, pWh, pS, nullptr,
                                                            NNODE, NNODE, FDIM);
    // 4) row softmax in place
    softmax_row<<<NNODE, 256>>>(pS, NNODE);

    // 5) O = S @ Wh + X                [8192,8192] @ [8192,512]
    sgemm128<false><<<dim3(FDIM / 128, NNODE / 128), blk>>>(pS, pWh, pO, X,
                                                            NNODE, FDIM, NNODE);
    // 6) batchnorm stats + 7) normalize + leaky relu
    colstats<<<dim3(FDIM / 128, 32), 256>>>();
    finalize_stats<<<1, FDIM>>>();
    normalize_out<<<(NNODE * FDIM) / 256, 256>>>((float*)d_out);
}